// round 1
// baseline (speedup 1.0000x reference)
#include <cuda_runtime.h>
#include <cstdint>
#include <math.h>

#define B_  2
#define T_  2048
#define C_  1024
#define H_  16
#define D_  64
#define BT_ 4096

// ---------------- scratch (allocation-free contract: __device__ globals) ----
__device__ float g_q[BT_ * C_];
__device__ float g_k[BT_ * C_];
__device__ float g_v[BT_ * C_];
__device__ float g_att[BT_ * C_];

// ---------------- generic SGEMM: C[M,N] = A[M,K] @ Bw[N,K]^T + bias --------
// 128x128 block tile, BK=16, 256 threads, 8x8 per-thread micro tile.
#define GM 128
#define GN 128
#define GK 16

__device__ __forceinline__ void sgemm_body(
    const float* __restrict__ A, const float* __restrict__ Bw,
    const float* __restrict__ bias, float* __restrict__ Cm,
    int M, int N, int K, int bx, int by)
{
    __shared__ float As[GK][GM];
    __shared__ float Bs[GK][GN];
    const int tid = threadIdx.x;
    const int tx  = tid & 15;
    const int ty  = tid >> 4;
    const int bm  = by * GM;
    const int bn  = bx * GN;
    const float* Ap = A  + (size_t)bm * K;
    const float* Bp = Bw + (size_t)bn * K;

    float acc[8][8];
#pragma unroll
    for (int i = 0; i < 8; ++i)
#pragma unroll
        for (int j = 0; j < 8; ++j) acc[i][j] = 0.f;

    for (int k0 = 0; k0 < K; k0 += GK) {
#pragma unroll
        for (int i = 0; i < 2; ++i) {
            int f  = tid + (i << 8);
            int r  = f >> 2;
            int c4 = (f & 3) << 2;
            float4 av = *(const float4*)(Ap + (size_t)r * K + k0 + c4);
            As[c4 + 0][r] = av.x; As[c4 + 1][r] = av.y;
            As[c4 + 2][r] = av.z; As[c4 + 3][r] = av.w;
            float4 bv = *(const float4*)(Bp + (size_t)r * K + k0 + c4);
            Bs[c4 + 0][r] = bv.x; Bs[c4 + 1][r] = bv.y;
            Bs[c4 + 2][r] = bv.z; Bs[c4 + 3][r] = bv.w;
        }
        __syncthreads();
#pragma unroll
        for (int kk = 0; kk < GK; ++kk) {
            float a[8], b[8];
            *(float4*)&a[0] = *(const float4*)&As[kk][ty * 8];
            *(float4*)&a[4] = *(const float4*)&As[kk][ty * 8 + 4];
            *(float4*)&b[0] = *(const float4*)&Bs[kk][tx * 8];
            *(float4*)&b[4] = *(const float4*)&Bs[kk][tx * 8 + 4];
#pragma unroll
            for (int i = 0; i < 8; ++i)
#pragma unroll
                for (int j = 0; j < 8; ++j)
                    acc[i][j] += a[i] * b[j];
        }
        __syncthreads();
    }

    float4 bias0 = *(const float4*)(bias + bn + tx * 8);
    float4 bias1 = *(const float4*)(bias + bn + tx * 8 + 4);
#pragma unroll
    for (int i = 0; i < 8; ++i) {
        float4 o0, o1;
        o0.x = acc[i][0] + bias0.x; o0.y = acc[i][1] + bias0.y;
        o0.z = acc[i][2] + bias0.z; o0.w = acc[i][3] + bias0.w;
        o1.x = acc[i][4] + bias1.x; o1.y = acc[i][5] + bias1.y;
        o1.z = acc[i][6] + bias1.z; o1.w = acc[i][7] + bias1.w;
        float* Cp = Cm + (size_t)(bm + ty * 8 + i) * N + bn + tx * 8;
        *(float4*)Cp       = o0;
        *(float4*)(Cp + 4) = o1;
    }
}

__global__ __launch_bounds__(256) void qkv_kernel(
    const float* __restrict__ x,
    const float* __restrict__ wq, const float* __restrict__ bq,
    const float* __restrict__ wk, const float* __restrict__ bk,
    const float* __restrict__ wv, const float* __restrict__ bv)
{
    const float* W; const float* bb; float* out;
    int z = blockIdx.z;
    if (z == 0)      { W = wq; bb = bq; out = g_q; }
    else if (z == 1) { W = wk; bb = bk; out = g_k; }
    else             { W = wv; bb = bv; out = g_v; }
    sgemm_body(x, W, bb, out, BT_, C_, C_, blockIdx.x, blockIdx.y);
}

__global__ __launch_bounds__(256) void out_kernel(
    const float* __restrict__ wo, const float* __restrict__ bo,
    float* __restrict__ out)
{
    sgemm_body(g_att, wo, bo, out, BT_, C_, C_, blockIdx.x, blockIdx.y);
}

// ---------------- RoPE (in-place on g_q, g_k; [BT, C] layout) --------------
// reference: rotate_half interleaved (out[2i]=-x[2i+1], out[2i+1]=x[2i]),
// freq table f(d) = 10000^(-2*(d&31)/64). Also folds 1/sqrt(D) into Q.
__global__ __launch_bounds__(256) void rope_kernel()
{
    int idx = blockIdx.x * 256 + threadIdx.x;      // over BT*C/2 pairs
    if (idx >= BT_ * C_ / 2) return;
    int row  = idx >> 9;          // / (C/2)
    int col2 = idx & 511;
    int t    = row & (T_ - 1);
    int d0   = (col2 << 1) & (D_ - 1);             // even d within head
    int j0   = d0 & 31;
    int j1   = (d0 + 1) & 31;
    // log2(10000)*2/64 = 0.41524103786091404
    float f0 = exp2f(-0.41524103786091404f * (float)j0);
    float f1 = exp2f(-0.41524103786091404f * (float)j1);
    float c0, s0, c1, s1;
    sincosf((float)t * f0, &s0, &c0);
    sincosf((float)t * f1, &s1, &c1);

    int base = row * C_ + (col2 << 1);
    float q0 = g_q[base], q1 = g_q[base + 1];
    g_q[base]     = (q0 * c0 - q1 * s0) * 0.125f;  // fold 1/sqrt(64)
    g_q[base + 1] = (q1 * c1 + q0 * s1) * 0.125f;
    float k0 = g_k[base], k1 = g_k[base + 1];
    g_k[base]     = k0 * c0 - k1 * s0;
    g_k[base + 1] = k1 * c1 + k0 * s1;
}

// ---------------- flash attention (fp32, Br=Bc=64) -------------------------
// grid: (T/64, B*H), 256 threads as 16x16, 4x4 register tiles.
// smem: Qt,Kt transposed [d][row] stride 65; Vs [row][d] stride 65; Ps [r][c].
#define FSTRIDE 65
#define FSMEM_BYTES (4 * 64 * FSTRIDE * 4)

__global__ __launch_bounds__(256) void flash_kernel()
{
    extern __shared__ float sm[];
    float* Qt = sm;
    float* Kt = Qt + 64 * FSTRIDE;
    float* Vs = Kt + 64 * FSTRIDE;
    float* Ps = Vs + 64 * FSTRIDE;

    const int bh = blockIdx.y;
    const int b  = bh >> 4;
    const int h  = bh & 15;
    const int t0 = blockIdx.x << 6;
    const int tid = threadIdx.x;
    const int tx = tid & 15;
    const int ty = tid >> 4;

    const float* Qg = g_q + ((size_t)(b * T_ + t0)) * C_ + h * D_;
#pragma unroll
    for (int it = 0; it < 4; ++it) {
        int idx = tid + (it << 8);
        int r = idx >> 4, d0 = (idx & 15) << 2;
        float4 qv = *(const float4*)(Qg + (size_t)r * C_ + d0);
        Qt[(d0 + 0) * FSTRIDE + r] = qv.x;
        Qt[(d0 + 1) * FSTRIDE + r] = qv.y;
        Qt[(d0 + 2) * FSTRIDE + r] = qv.z;
        Qt[(d0 + 3) * FSTRIDE + r] = qv.w;
    }

    float acc[4][4];
    float m_i[4], l_i[4];
#pragma unroll
    for (int i = 0; i < 4; ++i) {
        m_i[i] = -1e30f; l_i[i] = 0.f;
#pragma unroll
        for (int j = 0; j < 4; ++j) acc[i][j] = 0.f;
    }
    __syncthreads();

    for (int kt = 0; kt < T_ / 64; ++kt) {
        const float* Kg = g_k + ((size_t)(b * T_ + (kt << 6))) * C_ + h * D_;
        const float* Vg = g_v + ((size_t)(b * T_ + (kt << 6))) * C_ + h * D_;
#pragma unroll
        for (int it = 0; it < 4; ++it) {
            int idx = tid + (it << 8);
            int c = idx >> 4, d0 = (idx & 15) << 2;
            float4 kv = *(const float4*)(Kg + (size_t)c * C_ + d0);
            Kt[(d0 + 0) * FSTRIDE + c] = kv.x;
            Kt[(d0 + 1) * FSTRIDE + c] = kv.y;
            Kt[(d0 + 2) * FSTRIDE + c] = kv.z;
            Kt[(d0 + 3) * FSTRIDE + c] = kv.w;
            float4 vv = *(const float4*)(Vg + (size_t)c * C_ + d0);
            Vs[c * FSTRIDE + d0 + 0] = vv.x;
            Vs[c * FSTRIDE + d0 + 1] = vv.y;
            Vs[c * FSTRIDE + d0 + 2] = vv.z;
            Vs[c * FSTRIDE + d0 + 3] = vv.w;
        }
        __syncthreads();

        // S = Q @ K^T  (scale already folded into Q)
        float s[4][4];
#pragma unroll
        for (int i = 0; i < 4; ++i)
#pragma unroll
            for (int j = 0; j < 4; ++j) s[i][j] = 0.f;

#pragma unroll 8
        for (int d = 0; d < 64; ++d) {
            const float* qrow = &Qt[d * FSTRIDE + (ty << 2)];
            const float* krow = &Kt[d * FSTRIDE + (tx << 2)];
            float a0 = qrow[0], a1 = qrow[1], a2 = qrow[2], a3 = qrow[3];
            float b0 = krow[0], b1 = krow[1], b2 = krow[2], b3 = krow[3];
            s[0][0] += a0 * b0; s[0][1] += a0 * b1; s[0][2] += a0 * b2; s[0][3] += a0 * b3;
            s[1][0] += a1 * b0; s[1][1] += a1 * b1; s[1][2] += a1 * b2; s[1][3] += a1 * b3;
            s[2][0] += a2 * b0; s[2][1] += a2 * b1; s[2][2] += a2 * b2; s[2][3] += a2 * b3;
            s[3][0] += a3 * b0; s[3][1] += a3 * b1; s[3][2] += a3 * b2; s[3][3] += a3 * b3;
        }

        // online softmax per row (16-lane groups share a row set)
#pragma unroll
        for (int i = 0; i < 4; ++i) {
            float mx = fmaxf(fmaxf(s[i][0], s[i][1]), fmaxf(s[i][2], s[i][3]));
#pragma unroll
            for (int off = 8; off >= 1; off >>= 1)
                mx = fmaxf(mx, __shfl_xor_sync(0xffffffffu, mx, off));
            float m_new = fmaxf(m_i[i], mx);
            float corr  = __expf(m_i[i] - m_new);
            float rs = 0.f;
#pragma unroll
            for (int j = 0; j < 4; ++j) {
                float p = __expf(s[i][j] - m_new);
                s[i][j] = p;
                rs += p;
            }
#pragma unroll
            for (int off = 8; off >= 1; off >>= 1)
                rs += __shfl_xor_sync(0xffffffffu, rs, off);
            l_i[i] = l_i[i] * corr + rs;
            m_i[i] = m_new;
#pragma unroll
            for (int j = 0; j < 4; ++j) acc[i][j] *= corr;
#pragma unroll
            for (int j = 0; j < 4; ++j)
                Ps[(ty * 4 + i) * FSTRIDE + tx * 4 + j] = s[i][j];
        }
        __syncthreads();

        // O += P @ V
#pragma unroll 8
        for (int kk = 0; kk < 64; ++kk) {
            const float* vrow = &Vs[kk * FSTRIDE + (tx << 2)];
            float v0 = vrow[0], v1 = vrow[1], v2 = vrow[2], v3 = vrow[3];
            float p0 = Ps[(ty * 4 + 0) * FSTRIDE + kk];
            float p1 = Ps[(ty * 4 + 1) * FSTRIDE + kk];
            float p2 = Ps[(ty * 4 + 2) * FSTRIDE + kk];
            float p3 = Ps[(ty * 4 + 3) * FSTRIDE + kk];
            acc[0][0] += p0 * v0; acc[0][1] += p0 * v1; acc[0][2] += p0 * v2; acc[0][3] += p0 * v3;
            acc[1][0] += p1 * v0; acc[1][1] += p1 * v1; acc[1][2] += p1 * v2; acc[1][3] += p1 * v3;
            acc[2][0] += p2 * v0; acc[2][1] += p2 * v1; acc[2][2] += p2 * v2; acc[2][3] += p2 * v3;
            acc[3][0] += p3 * v0; acc[3][1] += p3 * v1; acc[3][2] += p3 * v2; acc[3][3] += p3 * v3;
        }
        __syncthreads();
    }

    // epilogue: divide by l, write concat-head layout [b, t, h*64+d]
    float* Og = g_att + ((size_t)(b * T_ + t0)) * C_ + h * D_;
#pragma unroll
    for (int i = 0; i < 4; ++i) {
        float inv = 1.f / l_i[i];
        float4 o;
        o.x = acc[i][0] * inv; o.y = acc[i][1] * inv;
        o.z = acc[i][2] * inv; o.w = acc[i][3] * inv;
        *(float4*)(Og + (size_t)(ty * 4 + i) * C_ + (tx << 2)) = o;
    }
}

// ---------------- launch ---------------------------------------------------
extern "C" void kernel_launch(void* const* d_in, const int* in_sizes, int n_in,
                              void* d_out, int out_size)
{
    const float* x  = (const float*)d_in[0];
    const float* wq = (const float*)d_in[1];
    const float* bq = (const float*)d_in[2];
    const float* wk = (const float*)d_in[3];
    const float* bk = (const float*)d_in[4];
    const float* wv = (const float*)d_in[5];
    const float* bv = (const float*)d_in[6];
    const float* wo = (const float*)d_in[7];
    const float* bo = (const float*)d_in[8];
    float* out = (float*)d_out;

    qkv_kernel<<<dim3(C_ / GN, BT_ / GM, 3), 256>>>(x, wq, bq, wk, bk, wv, bv);
    rope_kernel<<<(BT_ * C_ / 2 + 255) / 256, 256>>>();
    cudaFuncSetAttribute(flash_kernel,
                         cudaFuncAttributeMaxDynamicSharedMemorySize, FSMEM_BYTES);
    flash_kernel<<<dim3(T_ / 64, B_ * H_), 256, FSMEM_BYTES>>>();
    out_kernel<<<dim3(C_ / GN, BT_ / GM), 256>>>(wo, bo, out);
}

// round 2
// speedup vs baseline: 2.8961x; 2.8961x over previous
#include <cuda_runtime.h>
#include <cstdint>
#include <math.h>

#define B_  2
#define T_  2048
#define C_  1024
#define H_  16
#define D_  64
#define BT_ 4096

// ---------------- scratch (allocation-free contract: __device__ globals) ----
__device__ float g_q[BT_ * C_];
__device__ float g_k[BT_ * C_];
__device__ float g_v[BT_ * C_];
__device__ float g_att[BT_ * C_];

// ---------------- tf32 mma helpers -----------------------------------------
__device__ __forceinline__ uint32_t f2tf(float x) {
    uint32_t u;
    asm("cvt.rna.tf32.f32 %0, %1;" : "=r"(u) : "f"(x));
    return u;
}

__device__ __forceinline__ void mma_tf32(float c[4], const uint32_t a[4],
                                         const uint32_t b[2]) {
    asm volatile(
        "mma.sync.aligned.m16n8k8.row.col.f32.tf32.tf32.f32 "
        "{%0,%1,%2,%3}, {%4,%5,%6,%7}, {%8,%9}, {%0,%1,%2,%3};\n"
        : "+f"(c[0]), "+f"(c[1]), "+f"(c[2]), "+f"(c[3])
        : "r"(a[0]), "r"(a[1]), "r"(a[2]), "r"(a[3]),
          "r"(b[0]), "r"(b[1]));
}

// ---------------- tf32 GEMM: C[M,N] = A[M,K] @ W[N,K]^T + bias --------------
// block 128x128, BK=16, 256 threads = 8 warps (warp tile 32m x 64n).
// smem stride 20 words -> fragment LDS pattern (20*g+tg)%32 is conflict-free.
#define GSTR 20

__device__ __forceinline__ void gemm_tf32_body(
    const float* __restrict__ A, const float* __restrict__ W,
    const float* __restrict__ bias, float* __restrict__ Cm,
    int M, int N, int K, int bx, int by)
{
    __shared__ uint32_t Asu[128 * GSTR];
    __shared__ uint32_t Bsu[128 * GSTR];

    const int tid  = threadIdx.x;
    const int warp = tid >> 5;
    const int lane = tid & 31;
    const int g    = lane >> 2;
    const int tg   = lane & 3;
    const int wm   = warp & 3;       // 0..3 -> m offset
    const int wn   = warp >> 2;      // 0..1 -> n offset
    const int m0   = wm * 32;
    const int n0   = wn * 64;
    const int bm   = by * 128;
    const int bn   = bx * 128;

    const float* Ap = A + (size_t)bm * K;
    const float* Wp = W + (size_t)bn * K;

    float acc[2][8][4];
#pragma unroll
    for (int mt = 0; mt < 2; ++mt)
#pragma unroll
        for (int nt = 0; nt < 8; ++nt)
#pragma unroll
            for (int i = 0; i < 4; ++i) acc[mt][nt][i] = 0.f;

    const int r0 = tid >> 2;          // 0..63? no: 256 threads -> two iters
    const int c4 = (tid & 3) << 2;

    float4 ra[2], rb[2];
    // prefetch k-block 0
#pragma unroll
    for (int i = 0; i < 2; ++i) {
        int f = tid + (i << 8);
        int r = f >> 2, c = (f & 3) << 2;
        ra[i] = *(const float4*)(Ap + (size_t)r * K + c);
        rb[i] = *(const float4*)(Wp + (size_t)r * K + c);
    }

    const int NKB = K / 16;
    for (int kb = 0; kb < NKB; ++kb) {
#pragma unroll
        for (int i = 0; i < 2; ++i) {
            int f = tid + (i << 8);
            int r = f >> 2, c = (f & 3) << 2;
            uint32_t* pa = &Asu[r * GSTR + c];
            pa[0] = f2tf(ra[i].x); pa[1] = f2tf(ra[i].y);
            pa[2] = f2tf(ra[i].z); pa[3] = f2tf(ra[i].w);
            uint32_t* pb = &Bsu[r * GSTR + c];
            pb[0] = f2tf(rb[i].x); pb[1] = f2tf(rb[i].y);
            pb[2] = f2tf(rb[i].z); pb[3] = f2tf(rb[i].w);
        }
        __syncthreads();

        if (kb + 1 < NKB) {
            int kofs = (kb + 1) * 16;
#pragma unroll
            for (int i = 0; i < 2; ++i) {
                int f = tid + (i << 8);
                int r = f >> 2, c = (f & 3) << 2;
                ra[i] = *(const float4*)(Ap + (size_t)r * K + kofs + c);
                rb[i] = *(const float4*)(Wp + (size_t)r * K + kofs + c);
            }
        }

#pragma unroll
        for (int ks = 0; ks < 2; ++ks) {
            const int k0 = ks * 8;
            uint32_t a[2][4], b[8][2];
#pragma unroll
            for (int mt = 0; mt < 2; ++mt) {
                int row = m0 + mt * 16 + g;
                a[mt][0] = Asu[row * GSTR + k0 + tg];
                a[mt][1] = Asu[(row + 8) * GSTR + k0 + tg];
                a[mt][2] = Asu[row * GSTR + k0 + tg + 4];
                a[mt][3] = Asu[(row + 8) * GSTR + k0 + tg + 4];
            }
#pragma unroll
            for (int nt = 0; nt < 8; ++nt) {
                int rn = n0 + nt * 8 + g;
                b[nt][0] = Bsu[rn * GSTR + k0 + tg];
                b[nt][1] = Bsu[rn * GSTR + k0 + tg + 4];
            }
#pragma unroll
            for (int mt = 0; mt < 2; ++mt)
#pragma unroll
                for (int nt = 0; nt < 8; ++nt)
                    mma_tf32(acc[mt][nt], a[mt], b[nt]);
        }
        __syncthreads();
    }

    // epilogue
#pragma unroll
    for (int mt = 0; mt < 2; ++mt) {
        int row = bm + m0 + mt * 16 + g;
#pragma unroll
        for (int nt = 0; nt < 8; ++nt) {
            int col = bn + n0 + nt * 8 + (tg << 1);
            float bv0 = bias[col], bv1 = bias[col + 1];
            float2 o0 = make_float2(acc[mt][nt][0] + bv0, acc[mt][nt][1] + bv1);
            float2 o1 = make_float2(acc[mt][nt][2] + bv0, acc[mt][nt][3] + bv1);
            *(float2*)(Cm + (size_t)row * N + col)       = o0;
            *(float2*)(Cm + (size_t)(row + 8) * N + col) = o1;
        }
    }
    (void)r0; (void)c4;
}

__global__ __launch_bounds__(256) void qkv_kernel(
    const float* __restrict__ x,
    const float* __restrict__ wq, const float* __restrict__ bq,
    const float* __restrict__ wk, const float* __restrict__ bk,
    const float* __restrict__ wv, const float* __restrict__ bv)
{
    const float* W; const float* bb; float* out;
    int z = blockIdx.z;
    if (z == 0)      { W = wq; bb = bq; out = g_q; }
    else if (z == 1) { W = wk; bb = bk; out = g_k; }
    else             { W = wv; bb = bv; out = g_v; }
    gemm_tf32_body(x, W, bb, out, BT_, C_, C_, blockIdx.x, blockIdx.y);
}

__global__ __launch_bounds__(256) void out_kernel(
    const float* __restrict__ wo, const float* __restrict__ bo,
    float* __restrict__ out)
{
    gemm_tf32_body(g_att, wo, bo, out, BT_, C_, C_, blockIdx.x, blockIdx.y);
}

// ---------------- RoPE (in-place on g_q, g_k; [BT, C] layout) --------------
__global__ __launch_bounds__(256) void rope_kernel()
{
    int idx = blockIdx.x * 256 + threadIdx.x;      // over BT*C/2 pairs
    if (idx >= BT_ * C_ / 2) return;
    int row  = idx >> 9;
    int col2 = idx & 511;
    int t    = row & (T_ - 1);
    int d0   = (col2 << 1) & (D_ - 1);
    int j0   = d0 & 31;
    int j1   = (d0 + 1) & 31;
    float f0 = exp2f(-0.41524103786091404f * (float)j0);
    float f1 = exp2f(-0.41524103786091404f * (float)j1);
    float c0, s0, c1, s1;
    sincosf((float)t * f0, &s0, &c0);
    sincosf((float)t * f1, &s1, &c1);

    int base = row * C_ + (col2 << 1);
    float q0 = g_q[base], q1 = g_q[base + 1];
    g_q[base]     = (q0 * c0 - q1 * s0) * 0.125f;   // fold 1/sqrt(64)
    g_q[base + 1] = (q1 * c1 + q0 * s1) * 0.125f;
    float k0 = g_k[base], k1 = g_k[base + 1];
    g_k[base]     = k0 * c0 - k1 * s0;
    g_k[base + 1] = k1 * c1 + k0 * s1;
}

// ---------------- flash attention (tf32 mma, Br=Bc=64) ---------------------
// 128 threads = 4 warps, each warp owns 16 q-rows. All matmuls via m16n8k8.
// smem strides picked so each fragment LDS is bank-conflict-free.
#define FQ_STR 68
#define FK_STR 68
#define FV_STR 72
#define FP_STR 68
#define FL_QS   0
#define FL_KS   (64 * FQ_STR)
#define FL_VS   (FL_KS + 64 * FK_STR)
#define FL_PS   (FL_VS + 64 * FV_STR)
#define FL_WORDS (FL_PS + 64 * FP_STR)
#define FSMEM_BYTES (FL_WORDS * 4)

__global__ __launch_bounds__(128) void flash_kernel()
{
    extern __shared__ uint32_t sm[];
    uint32_t* Qs = sm + FL_QS;
    uint32_t* Ks = sm + FL_KS;
    uint32_t* Vs = sm + FL_VS;
    uint32_t* Ps = sm + FL_PS;

    const int bh = blockIdx.y;
    const int b  = bh >> 4;
    const int h  = bh & 15;
    const int t0 = blockIdx.x << 6;
    const int tid  = threadIdx.x;
    const int warp = tid >> 5;
    const int lane = tid & 31;
    const int g    = lane >> 2;
    const int tg   = lane & 3;
    const int m0   = warp << 4;            // warp's q-row base inside tile

    // load + convert Q (scale pre-folded by rope)
    const float* Qg = g_q + ((size_t)(b * T_ + t0)) * C_ + h * D_;
#pragma unroll
    for (int it = 0; it < 8; ++it) {
        int f = tid + (it << 7);
        int r = f >> 4, c = (f & 15) << 2;
        float4 v = *(const float4*)(Qg + (size_t)r * C_ + c);
        uint32_t* p = &Qs[r * FQ_STR + c];
        p[0] = f2tf(v.x); p[1] = f2tf(v.y); p[2] = f2tf(v.z); p[3] = f2tf(v.w);
    }

    float oacc[8][4];
    float m_r[2], l_r[2];
#pragma unroll
    for (int nt = 0; nt < 8; ++nt)
#pragma unroll
        for (int i = 0; i < 4; ++i) oacc[nt][i] = 0.f;
    m_r[0] = m_r[1] = -1e30f;
    l_r[0] = l_r[1] = 0.f;
    __syncthreads();

    for (int kt = 0; kt < T_ / 64; ++kt) {
        const float* Kg = g_k + ((size_t)(b * T_ + (kt << 6))) * C_ + h * D_;
        const float* Vg = g_v + ((size_t)(b * T_ + (kt << 6))) * C_ + h * D_;
#pragma unroll
        for (int it = 0; it < 8; ++it) {
            int f = tid + (it << 7);
            int r = f >> 4, c = (f & 15) << 2;
            float4 kv = *(const float4*)(Kg + (size_t)r * C_ + c);
            uint32_t* pk = &Ks[r * FK_STR + c];
            pk[0] = f2tf(kv.x); pk[1] = f2tf(kv.y);
            pk[2] = f2tf(kv.z); pk[3] = f2tf(kv.w);
            float4 vv = *(const float4*)(Vg + (size_t)r * C_ + c);
            uint32_t* pv = &Vs[r * FV_STR + c];
            pv[0] = f2tf(vv.x); pv[1] = f2tf(vv.y);
            pv[2] = f2tf(vv.z); pv[3] = f2tf(vv.w);
        }
        __syncthreads();

        // ---- S = Q @ K^T (fp32 acc) ----
        float sacc[8][4];
#pragma unroll
        for (int nt = 0; nt < 8; ++nt)
#pragma unroll
            for (int i = 0; i < 4; ++i) sacc[nt][i] = 0.f;

#pragma unroll
        for (int ks = 0; ks < 8; ++ks) {
            const int k0 = ks << 3;
            uint32_t a[4];
            int row = m0 + g;
            a[0] = Qs[row * FQ_STR + k0 + tg];
            a[1] = Qs[(row + 8) * FQ_STR + k0 + tg];
            a[2] = Qs[row * FQ_STR + k0 + tg + 4];
            a[3] = Qs[(row + 8) * FQ_STR + k0 + tg + 4];
#pragma unroll
            for (int nt = 0; nt < 8; ++nt) {
                uint32_t bfr[2];
                int rn = (nt << 3) + g;
                bfr[0] = Ks[rn * FK_STR + k0 + tg];
                bfr[1] = Ks[rn * FK_STR + k0 + tg + 4];
                mma_tf32(sacc[nt], a, bfr);
            }
        }

        // ---- online softmax (rows g and g+8 of this warp tile) ----
        float mx0 = -1e30f, mx1 = -1e30f;
#pragma unroll
        for (int nt = 0; nt < 8; ++nt) {
            mx0 = fmaxf(mx0, fmaxf(sacc[nt][0], sacc[nt][1]));
            mx1 = fmaxf(mx1, fmaxf(sacc[nt][2], sacc[nt][3]));
        }
        mx0 = fmaxf(mx0, __shfl_xor_sync(0xffffffffu, mx0, 1));
        mx0 = fmaxf(mx0, __shfl_xor_sync(0xffffffffu, mx0, 2));
        mx1 = fmaxf(mx1, __shfl_xor_sync(0xffffffffu, mx1, 1));
        mx1 = fmaxf(mx1, __shfl_xor_sync(0xffffffffu, mx1, 2));

        float mn0 = fmaxf(m_r[0], mx0);
        float mn1 = fmaxf(m_r[1], mx1);
        float corr0 = __expf(m_r[0] - mn0);
        float corr1 = __expf(m_r[1] - mn1);

        float rs0 = 0.f, rs1 = 0.f;
#pragma unroll
        for (int nt = 0; nt < 8; ++nt) {
            float p0 = __expf(sacc[nt][0] - mn0);
            float p1 = __expf(sacc[nt][1] - mn0);
            float p2 = __expf(sacc[nt][2] - mn1);
            float p3 = __expf(sacc[nt][3] - mn1);
            rs0 += p0 + p1;
            rs1 += p2 + p3;
            sacc[nt][0] = p0; sacc[nt][1] = p1;
            sacc[nt][2] = p2; sacc[nt][3] = p3;
        }
        rs0 += __shfl_xor_sync(0xffffffffu, rs0, 1);
        rs0 += __shfl_xor_sync(0xffffffffu, rs0, 2);
        rs1 += __shfl_xor_sync(0xffffffffu, rs1, 1);
        rs1 += __shfl_xor_sync(0xffffffffu, rs1, 2);

        l_r[0] = l_r[0] * corr0 + rs0;
        l_r[1] = l_r[1] * corr1 + rs1;
        m_r[0] = mn0;
        m_r[1] = mn1;

#pragma unroll
        for (int nt = 0; nt < 8; ++nt) {
            oacc[nt][0] *= corr0; oacc[nt][1] *= corr0;
            oacc[nt][2] *= corr1; oacc[nt][3] *= corr1;
        }

        // ---- write P (tf32) into warp-private smem rows ----
        {
            int row = m0 + g;
            int colb = (tg << 1);
#pragma unroll
            for (int nt = 0; nt < 8; ++nt) {
                uint2 u0 = make_uint2(f2tf(sacc[nt][0]), f2tf(sacc[nt][1]));
                uint2 u1 = make_uint2(f2tf(sacc[nt][2]), f2tf(sacc[nt][3]));
                *(uint2*)&Ps[row * FP_STR + (nt << 3) + colb]       = u0;
                *(uint2*)&Ps[(row + 8) * FP_STR + (nt << 3) + colb] = u1;
            }
        }
        __syncwarp();

        // ---- O += P @ V ----
#pragma unroll
        for (int ks = 0; ks < 8; ++ks) {
            const int k0 = ks << 3;
            uint32_t a[4];
            int row = m0 + g;
            a[0] = Ps[row * FP_STR + k0 + tg];
            a[1] = Ps[(row + 8) * FP_STR + k0 + tg];
            a[2] = Ps[row * FP_STR + k0 + tg + 4];
            a[3] = Ps[(row + 8) * FP_STR + k0 + tg + 4];
#pragma unroll
            for (int nt = 0; nt < 8; ++nt) {
                uint32_t bfr[2];
                bfr[0] = Vs[(k0 + tg) * FV_STR + (nt << 3) + g];
                bfr[1] = Vs[(k0 + tg + 4) * FV_STR + (nt << 3) + g];
                mma_tf32(oacc[nt], a, bfr);
            }
        }
        __syncthreads();
    }

    // ---- epilogue: normalize, write concat-head layout ----
    float inv0 = 1.f / l_r[0];
    float inv1 = 1.f / l_r[1];
    float* Og = g_att + ((size_t)(b * T_ + t0)) * C_ + h * D_;
    int row = m0 + g;
#pragma unroll
    for (int nt = 0; nt < 8; ++nt) {
        int col = (nt << 3) + (tg << 1);
        float2 o0 = make_float2(oacc[nt][0] * inv0, oacc[nt][1] * inv0);
        float2 o1 = make_float2(oacc[nt][2] * inv1, oacc[nt][3] * inv1);
        *(float2*)(Og + (size_t)row * C_ + col)       = o0;
        *(float2*)(Og + (size_t)(row + 8) * C_ + col) = o1;
    }
}

// ---------------- launch ---------------------------------------------------
extern "C" void kernel_launch(void* const* d_in, const int* in_sizes, int n_in,
                              void* d_out, int out_size)
{
    const float* x  = (const float*)d_in[0];
    const float* wq = (const float*)d_in[1];
    const float* bq = (const float*)d_in[2];
    const float* wk = (const float*)d_in[3];
    const float* bk = (const float*)d_in[4];
    const float* wv = (const float*)d_in[5];
    const float* bv = (const float*)d_in[6];
    const float* wo = (const float*)d_in[7];
    const float* bo = (const float*)d_in[8];
    float* out = (float*)d_out;

    qkv_kernel<<<dim3(C_ / 128, BT_ / 128, 3), 256>>>(x, wq, bq, wk, bk, wv, bv);
    rope_kernel<<<(BT_ * C_ / 2 + 255) / 256, 256>>>();
    cudaFuncSetAttribute(flash_kernel,
                         cudaFuncAttributeMaxDynamicSharedMemorySize, FSMEM_BYTES);
    flash_kernel<<<dim3(T_ / 64, B_ * H_), 128, FSMEM_BYTES>>>();
    out_kernel<<<dim3(C_ / 128, BT_ / 128), 256>>>(wo, bo, out);
}

// round 4
// speedup vs baseline: 3.0813x; 1.0640x over previous
#include <cuda_runtime.h>
#include <cstdint>
#include <math.h>

#define B_  2
#define T_  2048
#define C_  1024
#define H_  16
#define D_  64
#define BT_ 4096

// ---------------- scratch (allocation-free contract: __device__ globals) ----
__device__ float g_q[BT_ * C_];
__device__ float g_k[BT_ * C_];
__device__ float g_v[BT_ * C_];
__device__ float g_att[BT_ * C_];

// ---------------- tf32 mma helpers -----------------------------------------
__device__ __forceinline__ uint32_t f2tf(float x) {
    uint32_t u;
    asm("cvt.rna.tf32.f32 %0, %1;" : "=r"(u) : "f"(x));
    return u;
}

__device__ __forceinline__ void mma_tf32(float c[4], const uint32_t a[4],
                                         const uint32_t b[2]) {
    asm volatile(
        "mma.sync.aligned.m16n8k8.row.col.f32.tf32.tf32.f32 "
        "{%0,%1,%2,%3}, {%4,%5,%6,%7}, {%8,%9}, {%0,%1,%2,%3};\n"
        : "+f"(c[0]), "+f"(c[1]), "+f"(c[2]), "+f"(c[3])
        : "r"(a[0]), "r"(a[1]), "r"(a[2]), "r"(a[3]),
          "r"(b[0]), "r"(b[1]));
}

// rope on an (even, odd) in-head pair. Matches reference rotate_half-interleaved.
__device__ __forceinline__ void rope2(float& e, float& o, float t,
                                      float f0, float f1, float scale) {
    float s0, c0, s1, c1;
    sincosf(t * f0, &s0, &c0);
    sincosf(t * f1, &s1, &c1);
    float en = (e * c0 - o * s0) * scale;
    float on = (o * c1 + e * s1) * scale;
    e = en; o = on;
}

#define ROPE_LG 0.41524103786091404f   // log2(10000)*2/64

// ---------------- tf32 GEMM: C[M,N] = A[M,K] @ W[N,K]^T + bias --------------
// block 128x128, BK=16, 256 threads = 8 warps (warp tile 32m x 64n).
// Double-buffered smem (one __syncthreads per k-chunk) + register prefetch.
// mode: 0 = plain (out proj), 1 = Q (rope+scale+round), 2 = K (rope+round),
//       3 = V (round only).
#define GSTR 20

__device__ __forceinline__ void gemm_tf32_body(
    const float* __restrict__ A, const float* __restrict__ W,
    const float* __restrict__ bias, float* __restrict__ Cm,
    int bx, int by, int mode)
{
    __shared__ uint32_t Asu[2][128 * GSTR];
    __shared__ uint32_t Bsu[2][128 * GSTR];

    const int K = C_, N = C_;
    const int tid  = threadIdx.x;
    const int warp = tid >> 5;
    const int lane = tid & 31;
    const int g    = lane >> 2;
    const int tg   = lane & 3;
    const int m0   = (warp & 3) * 32;
    const int n0   = (warp >> 2) * 64;
    const int bm   = by * 128;
    const int bn   = bx * 128;

    const float* Ap = A + (size_t)bm * K;
    const float* Wp = W + (size_t)bn * K;

    float acc[2][8][4];
#pragma unroll
    for (int mt = 0; mt < 2; ++mt)
#pragma unroll
        for (int nt = 0; nt < 8; ++nt)
#pragma unroll
            for (int i = 0; i < 4; ++i) acc[mt][nt][i] = 0.f;

    float4 ra[2], rb[2];
#pragma unroll
    for (int i = 0; i < 2; ++i) {
        int f = tid + (i << 8);
        int r = f >> 2, c = (f & 3) << 2;
        ra[i] = *(const float4*)(Ap + (size_t)r * K + c);
        rb[i] = *(const float4*)(Wp + (size_t)r * K + c);
    }

    const int NKB = K / 16;   // 64
    for (int kb = 0; kb < NKB; ++kb) {
        uint32_t* As = Asu[kb & 1];
        uint32_t* Bs = Bsu[kb & 1];
#pragma unroll
        for (int i = 0; i < 2; ++i) {
            int f = tid + (i << 8);
            int r = f >> 2, c = (f & 3) << 2;
            uint32_t* pa = &As[r * GSTR + c];
            pa[0] = f2tf(ra[i].x); pa[1] = f2tf(ra[i].y);
            pa[2] = f2tf(ra[i].z); pa[3] = f2tf(ra[i].w);
            uint32_t* pb = &Bs[r * GSTR + c];
            pb[0] = f2tf(rb[i].x); pb[1] = f2tf(rb[i].y);
            pb[2] = f2tf(rb[i].z); pb[3] = f2tf(rb[i].w);
        }
        __syncthreads();

        if (kb + 1 < NKB) {
            int kofs = (kb + 1) * 16;
#pragma unroll
            for (int i = 0; i < 2; ++i) {
                int f = tid + (i << 8);
                int r = f >> 2, c = (f & 3) << 2;
                ra[i] = *(const float4*)(Ap + (size_t)r * K + kofs + c);
                rb[i] = *(const float4*)(Wp + (size_t)r * K + kofs + c);
            }
        }

#pragma unroll
        for (int ks = 0; ks < 2; ++ks) {
            const int k0 = ks * 8;
            uint32_t a[2][4], b[8][2];
#pragma unroll
            for (int mt = 0; mt < 2; ++mt) {
                int row = m0 + mt * 16 + g;
                a[mt][0] = As[row * GSTR + k0 + tg];
                a[mt][1] = As[(row + 8) * GSTR + k0 + tg];
                a[mt][2] = As[row * GSTR + k0 + tg + 4];
                a[mt][3] = As[(row + 8) * GSTR + k0 + tg + 4];
            }
#pragma unroll
            for (int nt = 0; nt < 8; ++nt) {
                int rn = n0 + nt * 8 + g;
                b[nt][0] = Bs[rn * GSTR + k0 + tg];
                b[nt][1] = Bs[rn * GSTR + k0 + tg + 4];
            }
#pragma unroll
            for (int mt = 0; mt < 2; ++mt)
#pragma unroll
                for (int nt = 0; nt < 8; ++nt)
                    mma_tf32(acc[mt][nt], a[mt], b[nt]);
        }
        // single sync per iter: next fill targets the other buffer; the
        // following iteration's sync protects buffer reuse two iters out.
    }

    // ---- epilogue: bias (+ optional rope/scale/round), write --------------
    const bool do_rope = (mode == 1 || mode == 2);
    const float rscale = (mode == 1) ? 0.125f : 1.f;
#pragma unroll
    for (int nt = 0; nt < 8; ++nt) {
        int col = bn + n0 + nt * 8 + (tg << 1);
        float2 bv = *(const float2*)(bias + col);
        float f0 = 0.f, f1 = 0.f;
        if (do_rope) {
            int d0 = col & (D_ - 1);
            f0 = exp2f(-ROPE_LG * (float)(d0 & 31));
            f1 = exp2f(-ROPE_LG * (float)((d0 + 1) & 31));
        }
#pragma unroll
        for (int mt = 0; mt < 2; ++mt) {
            int row = bm + m0 + mt * 16 + g;
            float e0 = acc[mt][nt][0] + bv.x, o0 = acc[mt][nt][1] + bv.y;
            float e1 = acc[mt][nt][2] + bv.x, o1 = acc[mt][nt][3] + bv.y;
            if (do_rope) {
                rope2(e0, o0, (float)(row & (T_ - 1)), f0, f1, rscale);
                rope2(e1, o1, (float)((row + 8) & (T_ - 1)), f0, f1, rscale);
            }
            float2 w0, w1;
            if (mode != 0) {
                w0.x = __uint_as_float(f2tf(e0));
                w0.y = __uint_as_float(f2tf(o0));
                w1.x = __uint_as_float(f2tf(e1));
                w1.y = __uint_as_float(f2tf(o1));
            } else {
                w0.x = e0; w0.y = o0;
                w1.x = e1; w1.y = o1;
            }
            *(float2*)(Cm + (size_t)row * N + col)       = w0;
            *(float2*)(Cm + (size_t)(row + 8) * N + col) = w1;
        }
    }
}

__global__ __launch_bounds__(256, 2) void qkv_kernel(
    const float* __restrict__ x,
    const float* __restrict__ wq, const float* __restrict__ bq,
    const float* __restrict__ wk, const float* __restrict__ bk,
    const float* __restrict__ wv, const float* __restrict__ bv)
{
    const float* W; const float* bb; float* out; int mode;
    int z = blockIdx.z;
    if (z == 0)      { W = wq; bb = bq; out = g_q; mode = 1; }
    else if (z == 1) { W = wk; bb = bk; out = g_k; mode = 2; }
    else             { W = wv; bb = bv; out = g_v; mode = 3; }
    gemm_tf32_body(x, W, bb, out, blockIdx.x, blockIdx.y, mode);
}

__global__ __launch_bounds__(256, 2) void out_kernel(
    const float* __restrict__ wo, const float* __restrict__ bo,
    float* __restrict__ out)
{
    gemm_tf32_body(g_att, wo, bo, out, blockIdx.x, blockIdx.y, 0);
}

// ---------------- flash attention (tf32 warp-mma, Br=128, Bc=64) -----------
// 256 threads = 8 warps, each warp owns 16 q-rows. Inputs in g_q/g_k/g_v are
// already tf32-rounded (and rope/scale applied), so fills are pure copies.
// K/V double-buffered + register prefetch: one __syncthreads per kt iter.
#define FQ_STR 68
#define FK_STR 68
#define FV_STR 72
#define FP_STR 68
#define FL_QS   0
#define FL_KS   (128 * FQ_STR)                 // 8704
#define FL_VS   (FL_KS + 2 * 64 * FK_STR)      // 17408
#define FL_PS   (FL_VS + 2 * 64 * FV_STR)      // 26624
#define FL_WORDS (FL_PS + 128 * FP_STR)        // 35328
#define FSMEM_BYTES (FL_WORDS * 4)             // 141312

__global__ __launch_bounds__(256) void flash_kernel()
{
    extern __shared__ uint32_t sm[];
    uint32_t* Qs  = sm + FL_QS;
    uint32_t* KsB = sm + FL_KS;
    uint32_t* VsB = sm + FL_VS;
    uint32_t* Ps  = sm + FL_PS;

    const int bh = blockIdx.y;
    const int b  = bh >> 4;
    const int h  = bh & 15;
    const int t0 = blockIdx.x << 7;
    const int tid  = threadIdx.x;
    const int warp = tid >> 5;
    const int lane = tid & 31;
    const int g    = lane >> 2;
    const int tg   = lane & 3;
    const int m0   = warp << 4;

    // load Q block (128 rows) — already tf32 bits
    const float* Qg = g_q + ((size_t)(b * T_ + t0)) * C_ + h * D_;
#pragma unroll
    for (int it = 0; it < 8; ++it) {
        int f = tid + (it << 8);
        int r = f >> 4, c = (f & 15) << 2;
        float4 v = *(const float4*)(Qg + (size_t)r * C_ + c);
        float* p = (float*)&Qs[r * FQ_STR + c];
        *(float2*)p       = make_float2(v.x, v.y);
        *(float2*)(p + 2) = make_float2(v.z, v.w);
    }

    float oacc[8][4];
    float m_r[2], l_r[2];
#pragma unroll
    for (int nt = 0; nt < 8; ++nt)
#pragma unroll
        for (int i = 0; i < 4; ++i) oacc[nt][i] = 0.f;
    m_r[0] = m_r[1] = -1e30f;
    l_r[0] = l_r[1] = 0.f;

    const float* Kg0 = g_k + ((size_t)(b * T_)) * C_ + h * D_;
    const float* Vg0 = g_v + ((size_t)(b * T_)) * C_ + h * D_;

    float4 pk[4], pv[4];
#pragma unroll
    for (int i = 0; i < 4; ++i) {
        int f = tid + (i << 8);
        int r = f >> 4, c = (f & 15) << 2;
        pk[i] = *(const float4*)(Kg0 + (size_t)r * C_ + c);
        pv[i] = *(const float4*)(Vg0 + (size_t)r * C_ + c);
    }

    const int NKT = T_ / 64;   // 32
    for (int kt = 0; kt < NKT; ++kt) {
        uint32_t* Kb = KsB + (kt & 1) * (64 * FK_STR);
        uint32_t* Vb = VsB + (kt & 1) * (64 * FV_STR);
#pragma unroll
        for (int i = 0; i < 4; ++i) {
            int f = tid + (i << 8);
            int r = f >> 4, c = (f & 15) << 2;
            float* kp = (float*)&Kb[r * FK_STR + c];
            *(float2*)kp       = make_float2(pk[i].x, pk[i].y);
            *(float2*)(kp + 2) = make_float2(pk[i].z, pk[i].w);
            *(float4*)&Vb[r * FV_STR + c] = pv[i];
        }
        __syncthreads();

        if (kt + 1 < NKT) {
            const float* Kg = Kg0 + (size_t)((kt + 1) << 6) * C_;
            const float* Vg = Vg0 + (size_t)((kt + 1) << 6) * C_;
#pragma unroll
            for (int i = 0; i < 4; ++i) {
                int f = tid + (i << 8);
                int r = f >> 4, c = (f & 15) << 2;
                pk[i] = *(const float4*)(Kg + (size_t)r * C_ + c);
                pv[i] = *(const float4*)(Vg + (size_t)r * C_ + c);
            }
        }

        // ---- S = Q @ K^T ----
        float sacc[8][4];
#pragma unroll
        for (int nt = 0; nt < 8; ++nt)
#pragma unroll
            for (int i = 0; i < 4; ++i) sacc[nt][i] = 0.f;

#pragma unroll
        for (int ks = 0; ks < 8; ++ks) {
            const int k0 = ks << 3;
            uint32_t a[4];
            int row = m0 + g;
            a[0] = Qs[row * FQ_STR + k0 + tg];
            a[1] = Qs[(row + 8) * FQ_STR + k0 + tg];
            a[2] = Qs[row * FQ_STR + k0 + tg + 4];
            a[3] = Qs[(row + 8) * FQ_STR + k0 + tg + 4];
#pragma unroll
            for (int nt = 0; nt < 8; ++nt) {
                uint32_t bfr[2];
                int rn = (nt << 3) + g;
                bfr[0] = Kb[rn * FK_STR + k0 + tg];
                bfr[1] = Kb[rn * FK_STR + k0 + tg + 4];
                mma_tf32(sacc[nt], a, bfr);
            }
        }

        // ---- online softmax ----
        float mx0 = -1e30f, mx1 = -1e30f;
#pragma unroll
        for (int nt = 0; nt < 8; ++nt) {
            mx0 = fmaxf(mx0, fmaxf(sacc[nt][0], sacc[nt][1]));
            mx1 = fmaxf(mx1, fmaxf(sacc[nt][2], sacc[nt][3]));
        }
        mx0 = fmaxf(mx0, __shfl_xor_sync(0xffffffffu, mx0, 1));
        mx0 = fmaxf(mx0, __shfl_xor_sync(0xffffffffu, mx0, 2));
        mx1 = fmaxf(mx1, __shfl_xor_sync(0xffffffffu, mx1, 1));
        mx1 = fmaxf(mx1, __shfl_xor_sync(0xffffffffu, mx1, 2));

        float mn0 = fmaxf(m_r[0], mx0);
        float mn1 = fmaxf(m_r[1], mx1);
        float corr0 = __expf(m_r[0] - mn0);
        float corr1 = __expf(m_r[1] - mn1);

        float rs0 = 0.f, rs1 = 0.f;
#pragma unroll
        for (int nt = 0; nt < 8; ++nt) {
            float p0 = __expf(sacc[nt][0] - mn0);
            float p1 = __expf(sacc[nt][1] - mn0);
            float p2 = __expf(sacc[nt][2] - mn1);
            float p3 = __expf(sacc[nt][3] - mn1);
            rs0 += p0 + p1;
            rs1 += p2 + p3;
            sacc[nt][0] = p0; sacc[nt][1] = p1;
            sacc[nt][2] = p2; sacc[nt][3] = p3;
        }
        rs0 += __shfl_xor_sync(0xffffffffu, rs0, 1);
        rs0 += __shfl_xor_sync(0xffffffffu, rs0, 2);
        rs1 += __shfl_xor_sync(0xffffffffu, rs1, 1);
        rs1 += __shfl_xor_sync(0xffffffffu, rs1, 2);

        l_r[0] = l_r[0] * corr0 + rs0;
        l_r[1] = l_r[1] * corr1 + rs1;
        m_r[0] = mn0;
        m_r[1] = mn1;

#pragma unroll
        for (int nt = 0; nt < 8; ++nt) {
            oacc[nt][0] *= corr0; oacc[nt][1] *= corr0;
            oacc[nt][2] *= corr1; oacc[nt][3] *= corr1;
        }

        // ---- write P (tf32) into warp-private smem rows ----
        {
            int row = m0 + g;
            int colb = (tg << 1);
#pragma unroll
            for (int nt = 0; nt < 8; ++nt) {
                uint2 u0 = make_uint2(f2tf(sacc[nt][0]), f2tf(sacc[nt][1]));
                uint2 u1 = make_uint2(f2tf(sacc[nt][2]), f2tf(sacc[nt][3]));
                *(uint2*)&Ps[row * FP_STR + (nt << 3) + colb]       = u0;
                *(uint2*)&Ps[(row + 8) * FP_STR + (nt << 3) + colb] = u1;
            }
        }
        __syncwarp();

        // ---- O += P @ V ----
#pragma unroll
        for (int ks = 0; ks < 8; ++ks) {
            const int k0 = ks << 3;
            uint32_t a[4];
            int row = m0 + g;
            a[0] = Ps[row * FP_STR + k0 + tg];
            a[1] = Ps[(row + 8) * FP_STR + k0 + tg];
            a[2] = Ps[row * FP_STR + k0 + tg + 4];
            a[3] = Ps[(row + 8) * FP_STR + k0 + tg + 4];
#pragma unroll
            for (int nt = 0; nt < 8; ++nt) {
                uint32_t bfr[2];
                bfr[0] = Vb[(k0 + tg) * FV_STR + (nt << 3) + g];
                bfr[1] = Vb[(k0 + tg + 4) * FV_STR + (nt << 3) + g];
                mma_tf32(oacc[nt], a, bfr);
            }
        }
        // no trailing sync: next fill writes the other K/V buffer
    }

    // ---- epilogue: normalize, write concat-head layout ----
    float inv0 = 1.f / l_r[0];
    float inv1 = 1.f / l_r[1];
    float* Og = g_att + ((size_t)(b * T_ + t0)) * C_ + h * D_;
    int row = m0 + g;
#pragma unroll
    for (int nt = 0; nt < 8; ++nt) {
        int col = (nt << 3) + (tg << 1);
        float2 o0 = make_float2(oacc[nt][0] * inv0, oacc[nt][1] * inv0);
        float2 o1 = make_float2(oacc[nt][2] * inv1, oacc[nt][3] * inv1);
        *(float2*)(Og + (size_t)row * C_ + col)       = o0;
        *(float2*)(Og + (size_t)(row + 8) * C_ + col) = o1;
    }
}

// ---------------- launch ---------------------------------------------------
extern "C" void kernel_launch(void* const* d_in, const int* in_sizes, int n_in,
                              void* d_out, int out_size)
{
    const float* x  = (const float*)d_in[0];
    const float* wq = (const float*)d_in[1];
    const float* bq = (const float*)d_in[2];
    const float* wk = (const float*)d_in[3];
    const float* bk = (const float*)d_in[4];
    const float* wv = (const float*)d_in[5];
    const float* bv = (const float*)d_in[6];
    const float* wo = (const float*)d_in[7];
    const float* bo = (const float*)d_in[8];
    float* out = (float*)d_out;

    cudaFuncSetAttribute(flash_kernel,
                         cudaFuncAttributeMaxDynamicSharedMemorySize, FSMEM_BYTES);

    qkv_kernel<<<dim3(C_ / 128, BT_ / 128, 3), 256>>>(x, wq, bq, wk, bk, wv, bv);
    flash_kernel<<<dim3(T_ / 128, B_ * H_), 256, FSMEM_BYTES>>>();
    out_kernel<<<dim3(C_ / 128, BT_ / 128), 256>>>(wo, bo, out);
}